// round 10
// baseline (speedup 1.0000x reference)
#include <cuda_runtime.h>
#include <cstdint>

// OneDilate: out = 10x10 depthwise box filter of (1-x)*0.5, replicate pad 4.
// x: [32,3,512,512] f32 -> out: [32,3,511,511] f32.
// out = 50 - 0.5 * (sum of 100 raw taps).
//
// Vertical-first separable filter:
//  - vertical sliding 10-sum per column, register ring of 10 (1 LDG/row)
//  - 10-row V chunks in smem, double-buffered, 1 barrier/chunk
//  - horizontal: 8 outputs/thread via 5 LDS.128 (conflict-free via VSTR%8==4
//    + uniform shift), global-aligned groups -> 2x STG.128 per thread
//  - per-row alignment phase d=(p+3*oy)&3 shifts smem so output groups are
//    16B-aligned in gmem; <=3 edge outputs/row via sliding-subtract.

#define IN_H   512
#define IN_W   512
#define OUT_H  511
#define OUT_W  511
#define PLANES 96
#define TILE_X 128
#define TILE_Y 40
#define CH     10
#define NCHUNK 4          // TILE_Y / CH
#define VW     137        // TILE_X + 9 vertical columns
#define VSTR   148        // row stride: %4==0 (align), %8==4 (bank interleave)
#define NT     160        // 5 warps

__global__ __launch_bounds__(NT)
void onedilate_kernel(const float* __restrict__ x, float* __restrict__ out)
{
    __shared__ __align__(16) float V[2][CH * VSTR];   // 11,840 B

    const int tx0 = blockIdx.x * TILE_X;
    const int ty0 = blockIdx.y * TILE_Y;
    const int p   = blockIdx.z;
    const float* __restrict__ xp = x   + (size_t)p * IN_H * IN_W;
    float* __restrict__       op = out + (size_t)p * OUT_H * OUT_W;
    const int t = threadIdx.x;

    // ---- vertical role: one input column per thread (clamped = replicate pad)
    int col = tx0 - 4 + t;
    col = (col < 0) ? 0 : (col > IN_W - 1 ? IN_W - 1 : col);
    const float* __restrict__ xc = xp + col;

    float ring[10];
    float vs = 0.0f;
    if (t < VW) {
        #pragma unroll
        for (int k = 0; k < 9; k++) {           // rows ty0-4 .. ty0+4 (clamped)
            int g = ty0 - 4 + k;
            g = (g < 0) ? 0 : (g > IN_H - 1 ? IN_H - 1 : g);
            ring[k] = xc[g * IN_W];
            vs += ring[k];
        }
    }
    ring[9] = 0.0f;   // slot 9 is written (jj=0) before it is read (jj=9)

    // ---- horizontal role: warp w covers rows (2w, 2w+1); even/odd lanes
    const int lane = t & 31;
    const int hrow = 2 * (t >> 5) + (lane & 1);   // 0..9
    const int hl   = lane >> 1;                   // 0..15, 8 output cols each
    const int lim  = (tx0 + TILE_X < OUT_W) ? (tx0 + TILE_X) : OUT_W;

    for (int ck = 0; ck < NCHUNK; ck++) {
        float* __restrict__ Vb = V[ck & 1];
        const int jb = ty0 + ck * CH;

        // -------- produce: 10 rows of vertical 10-sums (register ring)
        if (t < VW) {
            #pragma unroll
            for (int jj = 0; jj < CH; jj++) {
                int bot = jb + jj + 5;
                bot = (bot > IN_H - 1) ? IN_H - 1 : bot;
                float v = xc[bot * IN_W];
                vs += v;                                   // window [oy-4, oy+5]
                int d  = (p + 3 * (jb + jj)) & 3;          // gmem phase of row
                int dp = ((d - 1) & 3) + 1;                // 0->4, else d
                Vb[jj * VSTR + dp + t] = vs;               // col c at idx c+dp
                vs -= ring[jj];
                ring[(jj + 9) % 10] = v;
            }
        }
        __syncthreads();   // single barrier per chunk (double-buffered)

        // -------- consume: horizontal sliding 10-sum, 8 outputs per thread
        const int oy = jb + hrow;
        if (oy < OUT_H) {
            const int d  = (p + 3 * oy) & 3;
            const int a  = (4 - d) & 3;                    // leading edge count
            const float* __restrict__ row = Vb + hrow * VSTR;
            // base idx = 4 + 8*hl (uniform across lanes -> conflict-free)
            const float4* __restrict__ qp = (const float4*)(row + 4 + 8 * hl);
            float4 q0 = qp[0], q1 = qp[1], q2 = qp[2], q3 = qp[3], q4 = qp[4];
            float f[20] = {q0.x,q0.y,q0.z,q0.w, q1.x,q1.y,q1.z,q1.w,
                           q2.x,q2.y,q2.z,q2.w, q3.x,q3.y,q3.z,q3.w,
                           q4.x,q4.y,q4.z,q4.w};
            // f[k] = V col (a + 8*hl + k); output o=a+8hl+i sums f[i..i+9]
            float s0 = ((f[0]+f[1]) + (f[2]+f[3]))
                     + ((f[4]+f[5]) + (f[6]+f[7])) + (f[8]+f[9]);
            float s1 = s0 - f[0] + f[10];
            float s2 = s1 - f[1] + f[11];
            float s3 = s2 - f[2] + f[12];
            float s4 = s3 - f[3] + f[13];
            float s5 = s4 - f[4] + f[14];
            float s6 = s5 - f[5] + f[15];
            float s7 = s6 - f[6] + f[16];

            float* __restrict__ orow = op + (size_t)oy * OUT_W;
            const int ox = tx0 + a + 8 * hl;

            if (ox + 3 < lim) {
                *(float4*)(orow + ox) = make_float4(
                    fmaf(s0,-0.5f,50.0f), fmaf(s1,-0.5f,50.0f),
                    fmaf(s2,-0.5f,50.0f), fmaf(s3,-0.5f,50.0f));
            } else {
                if (ox+0 < lim) orow[ox+0] = fmaf(s0,-0.5f,50.0f);
                if (ox+1 < lim) orow[ox+1] = fmaf(s1,-0.5f,50.0f);
                if (ox+2 < lim) orow[ox+2] = fmaf(s2,-0.5f,50.0f);
            }
            const int ox2 = ox + 4;
            if (ox2 + 3 < lim) {
                *(float4*)(orow + ox2) = make_float4(
                    fmaf(s4,-0.5f,50.0f), fmaf(s5,-0.5f,50.0f),
                    fmaf(s6,-0.5f,50.0f), fmaf(s7,-0.5f,50.0f));
            } else {
                if (ox2+0 < lim) orow[ox2+0] = fmaf(s4,-0.5f,50.0f);
                if (ox2+1 < lim) orow[ox2+1] = fmaf(s5,-0.5f,50.0f);
                if (ox2+2 < lim) orow[ox2+2] = fmaf(s6,-0.5f,50.0f);
                if (ox2+3 < lim) orow[ox2+3] = fmaf(s7,-0.5f,50.0f);
            }

            // leading edge: cols tx0 .. tx0+a-1 (hl==0 lane, slide left of s0)
            if (hl == 0 && a > 0) {
                float4 m = *(const float4*)row;            // idx 0..3
                float qm[4] = {m.x, m.y, m.z, m.w};        // qm[3] = col a-1
                float sv = s0;                             // cols [a, a+9]
                #pragma unroll
                for (int k = 0; k < 3; k++) {
                    if (k < a) {
                        sv = sv - f[9 - k] + qm[3 - k];    // cols [a-1-k, a+8-k]
                        orow[tx0 + (a - 1 - k)] = fmaf(sv, -0.5f, 50.0f);
                    }
                }
            }
        }
        // no second barrier: next produce writes the other buffer, and the
        // sync above already ordered all consumes of chunk ck-1.
    }
}

extern "C" void kernel_launch(void* const* d_in, const int* in_sizes, int n_in,
                              void* d_out, int out_size)
{
    const float* x = (const float*)d_in[0];
    float* out = (float*)d_out;

    dim3 grid((OUT_W + TILE_X - 1) / TILE_X,   // 4
              (OUT_H + TILE_Y - 1) / TILE_Y,   // 13
              PLANES);                          // 96  -> 4992 CTAs
    onedilate_kernel<<<grid, NT>>>(x, out);
}

// round 11
// speedup vs baseline: 2.2935x; 2.2935x over previous
#include <cuda_runtime.h>
#include <cstdint>

// OneDilate: out = 10x10 depthwise box filter of (1-x)*0.5, replicate pad 4.
// x: [32,3,512,512] f32 -> out: [32,3,511,511] f32.
// out = 50 - 0.5 * (sum of 100 raw taps).
//
// R9 structure + two changes:
//  - vertical pass keeps last 16 loads in registers (bufA/bufB): 1 LDG/row
//    (no top re-read), top value comes from a register.
//  - software pipeline: next chunk's 16 LDGs issued before the barrier;
//    V double-buffered in smem -> ONE __syncthreads per chunk.

#define IN_H   512
#define IN_W   512
#define OUT_H  511
#define OUT_W  511
#define PLANES 96
#define TILE_X 128
#define TILE_Y 128
#define CH     16
#define NCHUNK 8           // TILE_Y / CH
#define VW     137         // TILE_X + 9 vertical columns
#define VSTR   140         // padded row stride (16B aligned, conflict-free)
#define NT     160         // 5 warps

// One pipeline step: produce V rows for chunk CK from CUR (regs), prefetch
// chunk CK+1 into NXT (regs), barrier, consume chunk CK from smem VB.
// top row value: for jj<=8 it was loaded in the previous chunk (NXT[jj+7]
// still holds it), for jj>=9 it is CUR[jj-9]. All indices compile-time.
#define STEP(CK, CUR, NXT, VB) do {                                          \
    const int jb = ty0 + (CK) * CH;                                          \
    if (vrole) {                                                             \
        _Pragma("unroll")                                                    \
        for (int jj = 0; jj < CH; jj++) {                                    \
            float v = CUR[jj];                                               \
            vs += v;                               /* rows [oy-4 .. oy+5] */ \
            VB[jj * VSTR + t] = vs;                                          \
            vs -= (jj <= 8) ? NXT[jj + 7] : CUR[jj - 9];                     \
        }                                                                    \
        if ((CK) < NCHUNK - 1) {                                             \
            _Pragma("unroll")                                                \
            for (int jj = 0; jj < CH; jj++) {                                \
                int g = jb + CH + jj + 5;                                    \
                g = (g > IN_H - 1) ? IN_H - 1 : g;                           \
                NXT[jj] = xc[g * IN_W];                                      \
            }                                                                \
        }                                                                    \
    }                                                                        \
    __syncthreads();                                                         \
    for (int item = t; item < CH * 32; item += NT) {                         \
        const int jj = item >> 5;                                            \
        const int l  = item & 31;                                            \
        const float4* __restrict__ Vv = (const float4*)(VB + jj*VSTR + 4*l); \
        float4 a = Vv[0], b = Vv[1], c4 = Vv[2], d = Vv[3];                  \
        float s0 = ((a.x + a.y) + (a.z + a.w))                               \
                 + ((b.x + b.y) + (b.z + b.w)) + (c4.x + c4.y);              \
        float s1 = s0 - a.x + c4.z;                                          \
        float s2 = s1 - a.y + c4.w;                                          \
        float s3 = s2 - a.z + d.x;                                           \
        const int oy = jb + jj;                                              \
        const int ox = tx0 + 4 * l;                                          \
        if (oy < OUT_H) {                                                    \
            float* __restrict__ o = op + (size_t)oy * OUT_W + ox;            \
            if (ox + 3 < OUT_W) {                                            \
                o[0] = fmaf(s0, -0.5f, 50.0f);                               \
                o[1] = fmaf(s1, -0.5f, 50.0f);                               \
                o[2] = fmaf(s2, -0.5f, 50.0f);                               \
                o[3] = fmaf(s3, -0.5f, 50.0f);                               \
            } else {                                                         \
                if (ox     < OUT_W) o[0] = fmaf(s0, -0.5f, 50.0f);           \
                if (ox + 1 < OUT_W) o[1] = fmaf(s1, -0.5f, 50.0f);           \
                if (ox + 2 < OUT_W) o[2] = fmaf(s2, -0.5f, 50.0f);           \
            }                                                                \
        }                                                                    \
    }                                                                        \
} while (0)

__global__ __launch_bounds__(NT)
void onedilate_kernel(const float* __restrict__ x, float* __restrict__ out)
{
    __shared__ __align__(16) float V[2][CH * VSTR];   // 17,920 B

    const int tx0 = blockIdx.x * TILE_X;
    const int ty0 = blockIdx.y * TILE_Y;
    const int p   = blockIdx.z;
    const float* __restrict__ xp = x   + (size_t)p * IN_H * IN_W;
    float* __restrict__       op = out + (size_t)p * OUT_H * OUT_W;
    const int t = threadIdx.x;

    // vertical role: one input column per thread (clamped = replicate pad)
    int col = tx0 - 4 + t;
    col = (col < 0) ? 0 : (col > IN_W - 1 ? IN_W - 1 : col);
    const float* __restrict__ xc = xp + col;
    const bool vrole = (t < VW);

    float bufA[CH], bufB[CH];
    float vs = 0.0f;

    if (vrole) {
        // warm-up history: rows ty0-4 .. ty0+4 (clamped) -> bufB[7..15]
        #pragma unroll
        for (int k = 0; k < 9; k++) {
            int g = ty0 - 4 + k;
            g = (g < 0) ? 0 : (g > IN_H - 1 ? IN_H - 1 : g);
            bufB[7 + k] = xc[g * IN_W];
            vs += bufB[7 + k];
        }
        // prefetch chunk 0: rows ty0+5 .. ty0+20 (clamped) -> bufA
        #pragma unroll
        for (int jj = 0; jj < CH; jj++) {
            int g = ty0 + 5 + jj;
            g = (g > IN_H - 1) ? IN_H - 1 : g;
            bufA[jj] = xc[g * IN_W];
        }
    }

    float* __restrict__ V0 = &V[0][0];
    float* __restrict__ V1 = &V[1][0];

    // single barrier per chunk: produce(ck+1) only happens after the barrier
    // of chunk ck+... each warp's consume(ck) precedes barrier(ck+1) in
    // program order, so produce(ck+2) into the same V buffer is ordered.
    for (int ck = 0; ck < NCHUNK; ck += 2) {
        STEP(ck,     bufA, bufB, V0);
        STEP(ck + 1, bufB, bufA, V1);
    }
}

extern "C" void kernel_launch(void* const* d_in, const int* in_sizes, int n_in,
                              void* d_out, int out_size)
{
    const float* x = (const float*)d_in[0];
    float* out = (float*)d_out;

    dim3 grid((OUT_W + TILE_X - 1) / TILE_X,   // 4
              (OUT_H + TILE_Y - 1) / TILE_Y,   // 4
              PLANES);                          // 96 -> 1536 CTAs (one wave)
    onedilate_kernel<<<grid, NT>>>(x, out);
}